// round 6
// baseline (speedup 1.0000x reference)
#include <cuda_runtime.h>
#include <cuda_bf16.h>
#include <math.h>
#include <stdint.h>

#define IN_DIM   784
#define HIDDEN   512
#define STYLE    128
#define BATCH    2048
#define NUM_LABELS 10

#define BM2 64                                  // fc2 row tile
#define MAX_TILES   (BATCH / BM2 + NUM_LABELS)  // 42 (64-gran, for fc2)
#define TILES128MAX (BATCH / 128 + NUM_LABELS)  // 26 (128-gran, for fc1)

// Scratch (no allocations allowed -> __device__ globals)
__device__ int   g_perm[BATCH];
__device__ int   g_tileGroup[MAX_TILES];
__device__ int   g_tileStart[MAX_TILES];
__device__ int   g_tileRows[MAX_TILES];
__device__ __nv_bfloat16 g_h1[(BATCH + 128) * HIDDEN];  // padded one 128-tile

// ---------------------------------------------------------------------------
// Helpers
// ---------------------------------------------------------------------------
__device__ __forceinline__ uint32_t f2bf2(float lo, float hi) {
    __nv_bfloat162 h = __floats2bfloat162_rn(lo, hi);
    return *reinterpret_cast<uint32_t*>(&h);
}

__device__ __forceinline__ void ldsm_x4(uint32_t& r0, uint32_t& r1, uint32_t& r2, uint32_t& r3,
                                        uint32_t saddr) {
    asm volatile("ldmatrix.sync.aligned.m8n8.x4.shared.b16 {%0,%1,%2,%3}, [%4];"
                 : "=r"(r0), "=r"(r1), "=r"(r2), "=r"(r3) : "r"(saddr));
}

__device__ __forceinline__ void ldsm_x4_t(uint32_t& r0, uint32_t& r1, uint32_t& r2, uint32_t& r3,
                                          uint32_t saddr) {
    asm volatile("ldmatrix.sync.aligned.m8n8.x4.trans.shared.b16 {%0,%1,%2,%3}, [%4];"
                 : "=r"(r0), "=r"(r1), "=r"(r2), "=r"(r3) : "r"(saddr));
}

__device__ __forceinline__ void mma16816_c(float* c, const uint32_t* a, const uint32_t* b) {
    asm volatile("mma.sync.aligned.m16n8k16.row.col.f32.bf16.bf16.f32 "
                 "{%0,%1,%2,%3}, {%4,%5,%6,%7}, {%8,%9}, {%0,%1,%2,%3};"
                 : "+f"(c[0]), "+f"(c[1]), "+f"(c[2]), "+f"(c[3])
                 : "r"(a[0]), "r"(a[1]), "r"(a[2]), "r"(a[3]), "r"(b[0]), "r"(b[1]));
}

// ---------------------------------------------------------------------------
// Kernel A: FC1 GEMM, 128x128 tile, BK=32, 512 threads (4x4 warps).
// Prologue: every block recomputes the label grouping deterministically
// (stable counting sort via smem histogram + warp scans, NO atomics).
// Block (0,0) publishes g_perm and the 64-granularity tile table for fc2.
// ---------------------------------------------------------------------------
__global__ __launch_bounds__(512, 1) void fc1_kernel(const float* __restrict__ x,
                                                     const int*   __restrict__ m,
                                                     const float* __restrict__ tab) {
    __shared__ __align__(16) __nv_bfloat16 As[2][128][40];   // 32 + 8 pad (20.0 KB)
    __shared__ __align__(16) __nv_bfloat16 Bs[2][32][136];   // 128 + 8 pad (17.0 KB)
    __shared__ int rowIdxS[128];
    __shared__ int cntS[NUM_LABELS];
    __shared__ int baseS[NUM_LABELS + 1];
    __shared__ int tb128[NUM_LABELS + 1];

    // histogram aliased onto As (used strictly before first As write)
    uint16_t (*h)[513] = reinterpret_cast<uint16_t(*)[513]>(&As[0][0][0]);

    const int t = threadIdx.x, lane = t & 31, warp = t >> 5;

    // ---- grouping prologue -------------------------------------------------
    int4 lv = ((const int4*)m)[t];              // 4 consecutive labels
    int lab[4] = {lv.x, lv.y, lv.z, lv.w};
#pragma unroll
    for (int g = 0; g < NUM_LABELS; g++) {
        int c = (lab[0] == g) + (lab[1] == g) + (lab[2] == g) + (lab[3] == g);
        h[g][t] = (uint16_t)c;
    }
    if (t < 128) rowIdxS[t] = -1;
    __syncthreads();

    if (warp < NUM_LABELS) {                    // warp w scans label w over 512 threads
        int s = 0;
#pragma unroll
        for (int j = 0; j < 16; j++) s += h[warp][lane * 16 + j];
        int incl = s;
#pragma unroll
        for (int d = 1; d < 32; d <<= 1) {
            int v = __shfl_up_sync(0xffffffffu, incl, d);
            if (lane >= d) incl += v;
        }
        int run = incl - s;                     // exclusive over lanes
#pragma unroll
        for (int j = 0; j < 16; j++) {
            int tt = lane * 16 + j;
            int v = h[warp][tt];
            h[warp][tt] = (uint16_t)run;        // exclusive over threads
            run += v;
        }
        if (lane == 31) cntS[warp] = run;
    }
    __syncthreads();

    if (t == 0) {
        int o = 0, tb = 0;
        for (int g = 0; g < NUM_LABELS; g++) {
            baseS[g] = o;  o  += cntS[g];
            tb128[g] = tb; tb += (cntS[g] + 127) >> 7;
        }
        baseS[NUM_LABELS] = o;
        tb128[NUM_LABELS] = tb;
    }
    __syncthreads();

    // my tile (128-granularity)
    const int myTile = blockIdx.y;
    int grp = -1, start = 0, rows = 0;
#pragma unroll
    for (int g = 0; g < NUM_LABELS; g++) {
        if (myTile >= tb128[g] && myTile < tb128[g + 1]) {
            grp = g;
            int j = myTile - tb128[g];
            start = baseS[g] + j * 128;
            rows  = min(128, cntS[g] - j * 128);
        }
    }

    // positions (stable) -> rowIdxS for my tile; block (0,0) publishes
    const bool pub = (blockIdx.x == 0 && blockIdx.y == 0);
#pragma unroll
    for (int e = 0; e < 4; e++) {
        int g = lab[e];
        int rank = 0;
#pragma unroll
        for (int e2 = 0; e2 < 4; e2++)
            if (e2 < e) rank += (lab[e2] == g);
        int pos = baseS[g] + (int)h[g][t] + rank;
        if (pos >= start && pos < start + 128) rowIdxS[pos - start] = t * 4 + e;
        if (pub) g_perm[pos] = t * 4 + e;
    }
    if (pub && t < MAX_TILES) {                 // 64-gran table for fc2
        int tb = 0, done = 0;
        for (int g = 0; g < NUM_LABELS; g++) {
            int nt = (cntS[g] + 63) >> 6;
            if (!done && t >= tb && t < tb + nt) {
                int j = t - tb;
                g_tileGroup[t] = g;
                g_tileStart[t] = baseS[g] + j * 64;
                g_tileRows[t]  = min(64, cntS[g] - j * 64);
                done = 1;
            }
            tb += nt;
        }
        if (!done) g_tileRows[t] = 0;
    }
    __syncthreads();
    if (grp < 0 || rows == 0) return;

    // ---- GEMM --------------------------------------------------------------
    const int n0 = blockIdx.x * 128;
    const float* W = tab + (size_t)grp * ((IN_DIM + 1) * HIDDEN);
    const int wm = warp >> 2, wn = warp & 3;    // 4 x 4 warp grid

    // A loads: 128x32 fp32 = 1024 float4, 2/thread
    int ar[2], ac4[2], alim[2]; const float* aptr[2];
#pragma unroll
    for (int p = 0; p < 2; p++) {
        int idx = t + p * 512;
        ar[p] = idx >> 3; ac4[p] = idx & 7;
        int gr = rowIdxS[ar[p]];
        aptr[p] = x + (size_t)max(gr, 0) * IN_DIM + ac4[p] * 4;
        alim[p] = (gr >= 0) ? (IN_DIM - ac4[p] * 4) : 0;
    }
    // B loads: 32x128 fp32 = 1024 float4, 2/thread
    int br[2], bc4[2];
#pragma unroll
    for (int p = 0; p < 2; p++) { int idx = t + p * 512; br[p] = idx >> 5; bc4[p] = idx & 31; }

    float acc[2][4][4];
#pragma unroll
    for (int mi = 0; mi < 2; mi++)
#pragma unroll
        for (int ni = 0; ni < 4; ni++)
#pragma unroll
            for (int j = 0; j < 4; j++) acc[mi][ni][j] = 0.f;

    const float4 Z4 = make_float4(0.f, 0.f, 0.f, 0.f);
    float4 aL[2], bL[2];
#pragma unroll
    for (int p = 0; p < 2; p++)
        aL[p] = (alim[p] > 0) ? *(const float4*)(aptr[p]) : Z4;
#pragma unroll
    for (int p = 0; p < 2; p++)
        bL[p] = *(const float4*)&W[(size_t)br[p] * HIDDEN + n0 + bc4[p] * 4];
#pragma unroll
    for (int p = 0; p < 2; p++) {
        *(uint32_t*)&As[0][ar[p]][ac4[p] * 4]     = f2bf2(aL[p].x, aL[p].y);
        *(uint32_t*)&As[0][ar[p]][ac4[p] * 4 + 2] = f2bf2(aL[p].z, aL[p].w);
    }
#pragma unroll
    for (int p = 0; p < 2; p++) {
        *(uint32_t*)&Bs[0][br[p]][bc4[p] * 4]     = f2bf2(bL[p].x, bL[p].y);
        *(uint32_t*)&Bs[0][br[p]][bc4[p] * 4 + 2] = f2bf2(bL[p].z, bL[p].w);
    }
    __syncthreads();

    const int NIT = (IN_DIM + 31) / 32;         // 25, last half-tile zero-filled
    for (int it = 0; it < NIT; ++it) {
        const int cur = it & 1;
        if (it + 1 < NIT) {
            const int k0 = (it + 1) * 32;
#pragma unroll
            for (int p = 0; p < 2; p++)
                aL[p] = (k0 < alim[p]) ? *(const float4*)(aptr[p] + k0) : Z4;
#pragma unroll
            for (int p = 0; p < 2; p++) {
                int kr = k0 + br[p];
                const float4 v = *(const float4*)&W[(size_t)min(kr, IN_DIM) * HIDDEN + n0 + bc4[p] * 4];
                bL[p] = (kr < IN_DIM) ? v : Z4;
            }
        }

        uint32_t a[2][2][4], b[2][4][2];
#pragma unroll
        for (int mi = 0; mi < 2; mi++)
#pragma unroll
            for (int kh = 0; kh < 2; kh++) {
                uint32_t sa = (uint32_t)__cvta_generic_to_shared(
                    &As[cur][wm * 32 + mi * 16 + (lane & 15)][kh * 16 + (lane >> 4) * 8]);
                ldsm_x4(a[mi][kh][0], a[mi][kh][1], a[mi][kh][2], a[mi][kh][3], sa);
            }
#pragma unroll
        for (int kh = 0; kh < 2; kh++)
#pragma unroll
            for (int half = 0; half < 2; half++) {
                uint32_t sb = (uint32_t)__cvta_generic_to_shared(
                    &Bs[cur][kh * 16 + (lane & 7) + ((lane >> 3) & 1) * 8]
                       [wn * 32 + half * 16 + (lane >> 4) * 8]);
                ldsm_x4_t(b[kh][2 * half][0], b[kh][2 * half][1],
                          b[kh][2 * half + 1][0], b[kh][2 * half + 1][1], sb);
            }
#pragma unroll
        for (int kh = 0; kh < 2; kh++)
#pragma unroll
            for (int mi = 0; mi < 2; mi++)
#pragma unroll
                for (int ni = 0; ni < 4; ni++)
                    mma16816_c(acc[mi][ni], a[mi][kh], b[kh][ni]);

        if (it + 1 < NIT) {
            const int nxt = cur ^ 1;
#pragma unroll
            for (int p = 0; p < 2; p++) {
                *(uint32_t*)&As[nxt][ar[p]][ac4[p] * 4]     = f2bf2(aL[p].x, aL[p].y);
                *(uint32_t*)&As[nxt][ar[p]][ac4[p] * 4 + 2] = f2bf2(aL[p].z, aL[p].w);
            }
#pragma unroll
            for (int p = 0; p < 2; p++) {
                *(uint32_t*)&Bs[nxt][br[p]][bc4[p] * 4]     = f2bf2(bL[p].x, bL[p].y);
                *(uint32_t*)&Bs[nxt][br[p]][bc4[p] * 4 + 2] = f2bf2(bL[p].z, bL[p].w);
            }
        }
        __syncthreads();
    }

    // Epilogue: +bias, ReLU, bf16 store to g_h1 (permuted dense rows)
    const float* bias = W + (size_t)IN_DIM * HIDDEN + n0;
    uint32_t* h1u = (uint32_t*)g_h1;
#pragma unroll
    for (int ni = 0; ni < 4; ni++) {
        int c = wn * 32 + ni * 8 + (lane & 3) * 2;
        float2 bb = *(const float2*)&bias[c];
#pragma unroll
        for (int mi = 0; mi < 2; mi++) {
            int r0 = wm * 32 + mi * 16 + (lane >> 2);
            if (r0 < rows) {
                float vx = fmaxf(acc[mi][ni][0] + bb.x, 0.f);
                float vy = fmaxf(acc[mi][ni][1] + bb.y, 0.f);
                h1u[((size_t)(start + r0) * HIDDEN + n0 + c) >> 1] = f2bf2(vx, vy);
            }
            int r1 = r0 + 8;
            if (r1 < rows) {
                float vx = fmaxf(acc[mi][ni][2] + bb.x, 0.f);
                float vy = fmaxf(acc[mi][ni][3] + bb.y, 0.f);
                h1u[((size_t)(start + r1) * HIDDEN + n0 + c) >> 1] = f2bf2(vx, vy);
            }
        }
    }
}

// ---------------------------------------------------------------------------
// Kernel B: FC2 GEMM (bf16 mma.sync). 64x128 tile, BK=32, 16 iters.
// Reads tables/perm published by fc1 block (0,0).
// ---------------------------------------------------------------------------
__global__ __launch_bounds__(256, 2) void fc2_kernel(const float* __restrict__ tab,
                                                     float* __restrict__ out) {
    const int tile = blockIdx.x;
    const int rows = g_tileRows[tile];
    if (rows == 0) return;
    const int grp   = g_tileGroup[tile];
    const int start = g_tileStart[tile];
    const float* W  = tab + (size_t)grp * ((HIDDEN + 1) * STYLE);

    __shared__ __align__(16) __nv_bfloat16 As[2][64][40];
    __shared__ __align__(16) __nv_bfloat16 Bs[2][32][136];
    __shared__ int rowIdx[64];

    const int t = threadIdx.x, lane = t & 31, warp = t >> 5;
    const int wm = warp >> 2, wn = warp & 3;

    if (t < 64) rowIdx[t] = (t < rows) ? g_perm[start + t] : -1;
    __syncthreads();

    const int ar = t >> 2, ah = t & 3;
    const uint4* aptr = (const uint4*)(g_h1 + (size_t)(start + ar) * HIDDEN + ah * 8);
    int br[4], bc4[4];
#pragma unroll
    for (int p = 0; p < 4; p++) { int idx = t + p * 256; br[p] = idx >> 5; bc4[p] = idx & 31; }

    float acc[2][4][4];
#pragma unroll
    for (int mi = 0; mi < 2; mi++)
#pragma unroll
        for (int ni = 0; ni < 4; ni++)
#pragma unroll
            for (int j = 0; j < 4; j++) acc[mi][ni][j] = 0.f;

    uint4 aL; float4 bL[4];
    aL = aptr[0];
#pragma unroll
    for (int p = 0; p < 4; p++)
        bL[p] = *(const float4*)&W[(size_t)br[p] * STYLE + bc4[p] * 4];
    *(uint4*)&As[0][ar][ah * 8] = aL;
#pragma unroll
    for (int p = 0; p < 4; p++) {
        *(uint32_t*)&Bs[0][br[p]][bc4[p] * 4]     = f2bf2(bL[p].x, bL[p].y);
        *(uint32_t*)&Bs[0][br[p]][bc4[p] * 4 + 2] = f2bf2(bL[p].z, bL[p].w);
    }
    __syncthreads();

    const int NIT = HIDDEN / 32;    // 16
    for (int it = 0; it < NIT; ++it) {
        const int cur = it & 1;
        if (it + 1 < NIT) {
            const int k0 = (it + 1) * 32;
            aL = *(const uint4*)((const __nv_bfloat16*)aptr + k0);
#pragma unroll
            for (int p = 0; p < 4; p++)
                bL[p] = *(const float4*)&W[(size_t)(k0 + br[p]) * STYLE + bc4[p] * 4];
        }

        uint32_t a[2][2][4], b[2][4][2];
#pragma unroll
        for (int mi = 0; mi < 2; mi++)
#pragma unroll
            for (int kh = 0; kh < 2; kh++) {
                uint32_t sa = (uint32_t)__cvta_generic_to_shared(
                    &As[cur][wm * 32 + mi * 16 + (lane & 15)][kh * 16 + (lane >> 4) * 8]);
                ldsm_x4(a[mi][kh][0], a[mi][kh][1], a[mi][kh][2], a[mi][kh][3], sa);
            }
#pragma unroll
        for (int kh = 0; kh < 2; kh++)
#pragma unroll
            for (int half = 0; half < 2; half++) {
                uint32_t sb = (uint32_t)__cvta_generic_to_shared(
                    &Bs[cur][kh * 16 + (lane & 7) + ((lane >> 3) & 1) * 8]
                       [wn * 32 + half * 16 + (lane >> 4) * 8]);
                ldsm_x4_t(b[kh][2 * half][0], b[kh][2 * half][1],
                          b[kh][2 * half + 1][0], b[kh][2 * half + 1][1], sb);
            }
#pragma unroll
        for (int kh = 0; kh < 2; kh++)
#pragma unroll
            for (int mi = 0; mi < 2; mi++)
#pragma unroll
                for (int ni = 0; ni < 4; ni++)
                    mma16816_c(acc[mi][ni], a[mi][kh], b[kh][ni]);

        if (it + 1 < NIT) {
            const int nxt = cur ^ 1;
            *(uint4*)&As[nxt][ar][ah * 8] = aL;
#pragma unroll
            for (int p = 0; p < 4; p++) {
                *(uint32_t*)&Bs[nxt][br[p]][bc4[p] * 4]     = f2bf2(bL[p].x, bL[p].y);
                *(uint32_t*)&Bs[nxt][br[p]][bc4[p] * 4 + 2] = f2bf2(bL[p].z, bL[p].w);
            }
        }
        __syncthreads();
    }

    // Epilogue: +bias, sigmoid, scatter fp32
    const float* bias = W + (size_t)HIDDEN * STYLE;
#pragma unroll
    for (int ni = 0; ni < 4; ni++) {
        int c = wn * 32 + ni * 8 + (lane & 3) * 2;
        float2 bb = *(const float2*)&bias[c];
#pragma unroll
        for (int mi = 0; mi < 2; mi++) {
            int r0 = wm * 32 + mi * 16 + (lane >> 2);
            if (r0 < rows) {
                int orow = rowIdx[r0];
                float2 v;
                v.x = 1.f / (1.f + __expf(-(acc[mi][ni][0] + bb.x)));
                v.y = 1.f / (1.f + __expf(-(acc[mi][ni][1] + bb.y)));
                *(float2*)&out[(size_t)orow * STYLE + c] = v;
            }
            int r1 = r0 + 8;
            if (r1 < rows) {
                int orow = rowIdx[r1];
                float2 v;
                v.x = 1.f / (1.f + __expf(-(acc[mi][ni][2] + bb.x)));
                v.y = 1.f / (1.f + __expf(-(acc[mi][ni][3] + bb.y)));
                *(float2*)&out[(size_t)orow * STYLE + c] = v;
            }
        }
    }
}

extern "C" void kernel_launch(void* const* d_in, const int* in_sizes, int n_in,
                              void* d_out, int out_size) {
    const float* x         = (const float*)d_in[0];
    const int*   m         = (const int*)d_in[1];
    const float* fc1_table = (const float*)d_in[2];
    const float* fc2_table = (const float*)d_in[3];
    float*       out       = (float*)d_out;

    fc1_kernel<<<dim3(HIDDEN / 128, TILES128MAX), 512>>>(x, m, fc1_table);
    fc2_kernel<<<MAX_TILES, 256>>>(fc2_table, out);
}

// round 7
// speedup vs baseline: 1.1171x; 1.1171x over previous
#include <cuda_runtime.h>
#include <cuda_bf16.h>
#include <math.h>
#include <stdint.h>

#define IN_DIM   784
#define HIDDEN   512
#define STYLE    128
#define BATCH    2048
#define NUM_LABELS 10

#define BM 64
#define MAX_TILES (BATCH / BM + NUM_LABELS)   // 42
#define KSPLIT 4                              // fc2 K split: 512 / 4 = 128 per chunk

// Scratch (no allocations allowed -> __device__ globals)
__device__ int   g_perm[BATCH];
__device__ int   g_tileGroup[MAX_TILES];
__device__ int   g_tileStart[MAX_TILES];
__device__ int   g_tileRows[MAX_TILES];
__device__ __nv_bfloat16 g_h1[(BATCH + 128) * HIDDEN];          // padded
__device__ float g_part[KSPLIT * BATCH * STYLE];                // fc2 partials, 4 MB

// ---------------------------------------------------------------------------
// Helpers
// ---------------------------------------------------------------------------
__device__ __forceinline__ uint32_t f2bf2(float lo, float hi) {
    __nv_bfloat162 h = __floats2bfloat162_rn(lo, hi);
    return *reinterpret_cast<uint32_t*>(&h);
}

__device__ __forceinline__ void ldsm_x4(uint32_t& r0, uint32_t& r1, uint32_t& r2, uint32_t& r3,
                                        uint32_t saddr) {
    asm volatile("ldmatrix.sync.aligned.m8n8.x4.shared.b16 {%0,%1,%2,%3}, [%4];"
                 : "=r"(r0), "=r"(r1), "=r"(r2), "=r"(r3) : "r"(saddr));
}

__device__ __forceinline__ void ldsm_x4_t(uint32_t& r0, uint32_t& r1, uint32_t& r2, uint32_t& r3,
                                          uint32_t saddr) {
    asm volatile("ldmatrix.sync.aligned.m8n8.x4.trans.shared.b16 {%0,%1,%2,%3}, [%4];"
                 : "=r"(r0), "=r"(r1), "=r"(r2), "=r"(r3) : "r"(saddr));
}

__device__ __forceinline__ void mma16816_c(float* c, const uint32_t* a, const uint32_t* b) {
    asm volatile("mma.sync.aligned.m16n8k16.row.col.f32.bf16.bf16.f32 "
                 "{%0,%1,%2,%3}, {%4,%5,%6,%7}, {%8,%9}, {%0,%1,%2,%3};"
                 : "+f"(c[0]), "+f"(c[1]), "+f"(c[2]), "+f"(c[3])
                 : "r"(a[0]), "r"(a[1]), "r"(a[2]), "r"(a[3]), "r"(b[0]), "r"(b[1]));
}

// ---------------------------------------------------------------------------
// Kernel 1: grouping, 32 blocks. Every block redundantly computes the
// deterministic atomic-free counting sort over the 8KB label array (L2
// broadcast); block b writes perm entries for input indices [b*64,(b+1)*64);
// block 0 writes the tile table. Stable -> fully deterministic.
// ---------------------------------------------------------------------------
__global__ void group_kernel(const int* __restrict__ m) {
    __shared__ uint16_t h[NUM_LABELS][257];
    __shared__ int cnt[NUM_LABELS];
    __shared__ int baseS[NUM_LABELS];
    const int t = threadIdx.x, lane = t & 31, warp = t >> 5;

    int4 lv0 = ((const int4*)m)[t * 2];
    int4 lv1 = ((const int4*)m)[t * 2 + 1];
    int lab[8] = {lv0.x, lv0.y, lv0.z, lv0.w, lv1.x, lv1.y, lv1.z, lv1.w};

#pragma unroll
    for (int g = 0; g < NUM_LABELS; g++) {
        int c = 0;
#pragma unroll
        for (int j = 0; j < 8; j++) c += (lab[j] == g);
        h[g][t] = (uint16_t)c;
    }
    __syncthreads();

    for (int g = warp; g < NUM_LABELS; g += 8) {
        int s = 0;
#pragma unroll
        for (int j = 0; j < 8; j++) s += h[g][lane * 8 + j];
        int incl = s;
#pragma unroll
        for (int d = 1; d < 32; d <<= 1) {
            int v = __shfl_up_sync(0xffffffffu, incl, d);
            if (lane >= d) incl += v;
        }
        int run = incl - s;
#pragma unroll
        for (int j = 0; j < 8; j++) {
            int tt = lane * 8 + j;
            int v = h[g][tt];
            h[g][tt] = (uint16_t)run;
            run += v;
        }
        if (lane == 31) cnt[g] = run;
    }
    __syncthreads();

    if (t == 0) {
        int o = 0;
        for (int g = 0; g < NUM_LABELS; g++) { baseS[g] = o; o += cnt[g]; }
        if (blockIdx.x == 0) {                          // tile table
            int tile = 0;
            for (int g = 0; g < NUM_LABELS; g++) {
                int c = cnt[g], nt = (c + BM - 1) / BM;
                for (int j = 0; j < nt; j++) {
                    g_tileGroup[tile] = g;
                    g_tileStart[tile] = baseS[g] + j * BM;
                    g_tileRows[tile]  = min(BM, c - j * BM);
                    tile++;
                }
            }
            for (; tile < MAX_TILES; tile++) g_tileRows[tile] = 0;
        }
    }
    __syncthreads();

    if ((t >> 3) == (int)blockIdx.x) {                  // this block's 8 threads write
#pragma unroll
        for (int j = 0; j < 8; j++) {
            int g = lab[j];
            int rank = 0;
#pragma unroll
            for (int j2 = 0; j2 < 8; j2++)
                if (j2 < j) rank += (lab[j2] == g);
            g_perm[baseS[g] + (int)h[g][t] + rank] = t * 8 + j;
        }
    }
}

// ---------------------------------------------------------------------------
// Kernel 2: FC1 GEMM (R5 winner): 64x128 tile, BK=32, 256 thr, occ 2.
// ---------------------------------------------------------------------------
__global__ __launch_bounds__(256, 2) void fc1_kernel(const float* __restrict__ x,
                                                     const float* __restrict__ tab) {
    const int tile = blockIdx.y;
    const int rows = g_tileRows[tile];
    if (rows == 0) return;
    const int grp   = g_tileGroup[tile];
    const int start = g_tileStart[tile];
    const int n0    = blockIdx.x * 128;
    const float* W  = tab + (size_t)grp * ((IN_DIM + 1) * HIDDEN);

    __shared__ __align__(16) __nv_bfloat16 As[2][64][40];
    __shared__ __align__(16) __nv_bfloat16 Bs[2][32][136];
    __shared__ int rowIdx[64];

    const int t = threadIdx.x, lane = t & 31, warp = t >> 5;
    const int wm = warp >> 2, wn = warp & 3;

    if (t < 64) rowIdx[t] = (t < rows) ? g_perm[start + t] : -1;
    __syncthreads();

    int ar[2], ac4[2], alim[2]; const float* aptr[2];
#pragma unroll
    for (int p = 0; p < 2; p++) {
        int idx = t + p * 256;
        ar[p] = idx >> 3; ac4[p] = idx & 7;
        int gr = rowIdx[ar[p]];
        aptr[p] = x + (size_t)max(gr, 0) * IN_DIM + ac4[p] * 4;
        alim[p] = (gr >= 0) ? (IN_DIM - ac4[p] * 4) : 0;
    }
    int br[4], bc4[4];
#pragma unroll
    for (int p = 0; p < 4; p++) { int idx = t + p * 256; br[p] = idx >> 5; bc4[p] = idx & 31; }

    float acc[2][4][4];
#pragma unroll
    for (int mi = 0; mi < 2; mi++)
#pragma unroll
        for (int ni = 0; ni < 4; ni++)
#pragma unroll
            for (int j = 0; j < 4; j++) acc[mi][ni][j] = 0.f;

    const float4 Z4 = make_float4(0.f, 0.f, 0.f, 0.f);
    float4 aL[2], bL[4];
#pragma unroll
    for (int p = 0; p < 2; p++)
        aL[p] = (alim[p] > 0) ? *(const float4*)(aptr[p]) : Z4;
#pragma unroll
    for (int p = 0; p < 4; p++)
        bL[p] = *(const float4*)&W[(size_t)br[p] * HIDDEN + n0 + bc4[p] * 4];
#pragma unroll
    for (int p = 0; p < 2; p++) {
        *(uint32_t*)&As[0][ar[p]][ac4[p] * 4]     = f2bf2(aL[p].x, aL[p].y);
        *(uint32_t*)&As[0][ar[p]][ac4[p] * 4 + 2] = f2bf2(aL[p].z, aL[p].w);
    }
#pragma unroll
    for (int p = 0; p < 4; p++) {
        *(uint32_t*)&Bs[0][br[p]][bc4[p] * 4]     = f2bf2(bL[p].x, bL[p].y);
        *(uint32_t*)&Bs[0][br[p]][bc4[p] * 4 + 2] = f2bf2(bL[p].z, bL[p].w);
    }
    __syncthreads();

    const int NIT = (IN_DIM + 31) / 32;    // 25
    for (int it = 0; it < NIT; ++it) {
        const int cur = it & 1;
        if (it + 1 < NIT) {
            const int k0 = (it + 1) * 32;
#pragma unroll
            for (int p = 0; p < 2; p++)
                aL[p] = (k0 < alim[p]) ? *(const float4*)(aptr[p] + k0) : Z4;
#pragma unroll
            for (int p = 0; p < 4; p++) {
                int kr = k0 + br[p];
                const float4 v = *(const float4*)&W[(size_t)min(kr, IN_DIM) * HIDDEN + n0 + bc4[p] * 4];
                bL[p] = (kr < IN_DIM) ? v : Z4;
            }
        }

        uint32_t a[2][2][4], b[2][4][2];
#pragma unroll
        for (int mi = 0; mi < 2; mi++)
#pragma unroll
            for (int kh = 0; kh < 2; kh++) {
                uint32_t sa = (uint32_t)__cvta_generic_to_shared(
                    &As[cur][wm * 32 + mi * 16 + (lane & 15)][kh * 16 + (lane >> 4) * 8]);
                ldsm_x4(a[mi][kh][0], a[mi][kh][1], a[mi][kh][2], a[mi][kh][3], sa);
            }
#pragma unroll
        for (int kh = 0; kh < 2; kh++)
#pragma unroll
            for (int half = 0; half < 2; half++) {
                uint32_t sb = (uint32_t)__cvta_generic_to_shared(
                    &Bs[cur][kh * 16 + (lane & 7) + ((lane >> 3) & 1) * 8]
                       [wn * 32 + half * 16 + (lane >> 4) * 8]);
                ldsm_x4_t(b[kh][2 * half][0], b[kh][2 * half][1],
                          b[kh][2 * half + 1][0], b[kh][2 * half + 1][1], sb);
            }
#pragma unroll
        for (int kh = 0; kh < 2; kh++)
#pragma unroll
            for (int mi = 0; mi < 2; mi++)
#pragma unroll
                for (int ni = 0; ni < 4; ni++)
                    mma16816_c(acc[mi][ni], a[mi][kh], b[kh][ni]);

        if (it + 1 < NIT) {
            const int nxt = cur ^ 1;
#pragma unroll
            for (int p = 0; p < 2; p++) {
                *(uint32_t*)&As[nxt][ar[p]][ac4[p] * 4]     = f2bf2(aL[p].x, aL[p].y);
                *(uint32_t*)&As[nxt][ar[p]][ac4[p] * 4 + 2] = f2bf2(aL[p].z, aL[p].w);
            }
#pragma unroll
            for (int p = 0; p < 4; p++) {
                *(uint32_t*)&Bs[nxt][br[p]][bc4[p] * 4]     = f2bf2(bL[p].x, bL[p].y);
                *(uint32_t*)&Bs[nxt][br[p]][bc4[p] * 4 + 2] = f2bf2(bL[p].z, bL[p].w);
            }
        }
        __syncthreads();
    }

    const float* bias = W + (size_t)IN_DIM * HIDDEN + n0;
    uint32_t* h1u = (uint32_t*)g_h1;
#pragma unroll
    for (int ni = 0; ni < 4; ni++) {
        int c = wn * 32 + ni * 8 + (lane & 3) * 2;
        float2 bb = *(const float2*)&bias[c];
#pragma unroll
        for (int mi = 0; mi < 2; mi++) {
            int r0 = wm * 32 + mi * 16 + (lane >> 2);
            if (r0 < rows) {
                float vx = fmaxf(acc[mi][ni][0] + bb.x, 0.f);
                float vy = fmaxf(acc[mi][ni][1] + bb.y, 0.f);
                h1u[((size_t)(start + r0) * HIDDEN + n0 + c) >> 1] = f2bf2(vx, vy);
            }
            int r1 = r0 + 8;
            if (r1 < rows) {
                float vx = fmaxf(acc[mi][ni][2] + bb.x, 0.f);
                float vy = fmaxf(acc[mi][ni][3] + bb.y, 0.f);
                h1u[((size_t)(start + r1) * HIDDEN + n0 + c) >> 1] = f2bf2(vx, vy);
            }
        }
    }
}

// ---------------------------------------------------------------------------
// Kernel 3: FC2 split-K partial. grid (42 tiles, 4 kchunks) = 168 blocks.
// Each: 64x128 output for K=128 (2 macro-iters of BK=64). Partials -> g_part.
// ---------------------------------------------------------------------------
__global__ __launch_bounds__(256, 2) void fc2p_kernel(const float* __restrict__ tab) {
    const int tile = blockIdx.x;
    const int kc   = blockIdx.y;
    const int rows = g_tileRows[tile];
    if (rows == 0) return;
    const int grp   = g_tileGroup[tile];
    const int start = g_tileStart[tile];
    const float* W  = tab + (size_t)grp * ((HIDDEN + 1) * STYLE) + (size_t)(kc * 128) * STYLE;

    __shared__ __align__(16) __nv_bfloat16 As[64][136];   // 64 rows x K=128 (+8 pad)
    __shared__ __align__(16) __nv_bfloat16 Bs[64][136];   // 64 K-rows x N=128 (+8 pad)

    const int t = threadIdx.x, lane = t & 31, warp = t >> 5;
    const int wm = warp >> 2, wn = warp & 3;

    // Load A in full: 64 rows x 128 bf16 from g_h1 (permuted dense) = 512 uint4
    {
        const __nv_bfloat16* h1 = g_h1 + (size_t)start * HIDDEN + kc * 128;
#pragma unroll
        for (int p = 0; p < 2; p++) {
            int idx = t + p * 256;
            int r = idx >> 3, q = idx & 7;
            *(uint4*)&As[r][q * 8] = *(const uint4*)(h1 + (size_t)r * HIDDEN + q * 8);
        }
    }

    float acc[2][4][4];
#pragma unroll
    for (int mi = 0; mi < 2; mi++)
#pragma unroll
        for (int ni = 0; ni < 4; ni++)
#pragma unroll
            for (int j = 0; j < 4; j++) acc[mi][ni][j] = 0.f;

    const int brw = t >> 3, bq = t & 7;   // 64 rows x 8 float4-cols, 2 rows/thread... (256thr->64x8/256=2)
#pragma unroll
    for (int h2 = 0; h2 < 2; h2++) {
        // Load B half: W rows h2*64..+64, 128 cols fp32 -> bf16. 64x32 float4 = 2048, 8/thread
#pragma unroll
        for (int p = 0; p < 8; p++) {
            int idx = t + p * 256;
            int r = idx >> 5, c4 = idx & 31;
            float4 v = *(const float4*)&W[(size_t)(h2 * 64 + r) * STYLE + c4 * 4];
            *(uint32_t*)&Bs[r][c4 * 4]     = f2bf2(v.x, v.y);
            *(uint32_t*)&Bs[r][c4 * 4 + 2] = f2bf2(v.z, v.w);
        }
        __syncthreads();

#pragma unroll
        for (int kh = 0; kh < 4; kh++) {
            uint32_t a[2][4], b[4][2];
#pragma unroll
            for (int mi = 0; mi < 2; mi++) {
                uint32_t sa = (uint32_t)__cvta_generic_to_shared(
                    &As[wm * 32 + mi * 16 + (lane & 15)][h2 * 64 + kh * 16 + (lane >> 4) * 8]);
                ldsm_x4(a[mi][0], a[mi][1], a[mi][2], a[mi][3], sa);
            }
#pragma unroll
            for (int half = 0; half < 2; half++) {
                uint32_t sb = (uint32_t)__cvta_generic_to_shared(
                    &Bs[kh * 16 + (lane & 7) + ((lane >> 3) & 1) * 8]
                       [wn * 32 + half * 16 + (lane >> 4) * 8]);
                ldsm_x4_t(b[2 * half][0], b[2 * half][1], b[2 * half + 1][0], b[2 * half + 1][1], sb);
            }
#pragma unroll
            for (int mi = 0; mi < 2; mi++)
#pragma unroll
                for (int ni = 0; ni < 4; ni++)
                    mma16816_c(acc[mi][ni], a[mi], b[ni]);
        }
        __syncthreads();
    }
    (void)brw; (void)bq;

    // Store partials (permuted dense rows, no bias/activation)
    float* P = g_part + (size_t)kc * BATCH * STYLE;
#pragma unroll
    for (int ni = 0; ni < 4; ni++) {
        int c = wn * 32 + ni * 8 + (lane & 3) * 2;
#pragma unroll
        for (int mi = 0; mi < 2; mi++) {
            int r0 = wm * 32 + mi * 16 + (lane >> 2);
            if (r0 < rows)
                *(float2*)&P[(size_t)(start + r0) * STYLE + c] =
                    make_float2(acc[mi][ni][0], acc[mi][ni][1]);
            int r1 = r0 + 8;
            if (r1 < rows)
                *(float2*)&P[(size_t)(start + r1) * STYLE + c] =
                    make_float2(acc[mi][ni][2], acc[mi][ni][3]);
        }
    }
}

// ---------------------------------------------------------------------------
// Kernel 4: combine partials + bias + sigmoid + scatter. 42 blocks.
// ---------------------------------------------------------------------------
__global__ __launch_bounds__(256) void combine_kernel(const float* __restrict__ tab,
                                                      float* __restrict__ out) {
    const int tile = blockIdx.x;
    const int rows = g_tileRows[tile];
    if (rows == 0) return;
    const int grp   = g_tileGroup[tile];
    const int start = g_tileStart[tile];
    const float* bias = tab + (size_t)grp * ((HIDDEN + 1) * STYLE) + (size_t)HIDDEN * STYLE;

    __shared__ int rowIdx[64];
    const int t = threadIdx.x;
    if (t < 64) rowIdx[t] = (t < rows) ? g_perm[start + t] : 0;
    __syncthreads();

    const int c4 = t & 31;                    // constant per thread
    float4 bb = *(const float4*)&bias[c4 * 4];

    for (int i = t; i < 64 * 32; i += 256) {  // float4 granularity
        int r = i >> 5;
        if (r >= rows) break;                 // rows-major loop: safe to stop
        size_t off = (size_t)(start + r) * STYLE + c4 * 4;
        float4 s0 = *(const float4*)&g_part[off];
        float4 s1 = *(const float4*)&g_part[(size_t)1 * BATCH * STYLE + off];
        float4 s2 = *(const float4*)&g_part[(size_t)2 * BATCH * STYLE + off];
        float4 s3 = *(const float4*)&g_part[(size_t)3 * BATCH * STYLE + off];
        float4 v;
        v.x = 1.f / (1.f + __expf(-(s0.x + s1.x + s2.x + s3.x + bb.x)));
        v.y = 1.f / (1.f + __expf(-(s0.y + s1.y + s2.y + s3.y + bb.y)));
        v.z = 1.f / (1.f + __expf(-(s0.z + s1.z + s2.z + s3.z + bb.z)));
        v.w = 1.f / (1.f + __expf(-(s0.w + s1.w + s2.w + s3.w + bb.w)));
        *(float4*)&out[(size_t)rowIdx[r] * STYLE + c4 * 4] = v;
    }
}

extern "C" void kernel_launch(void* const* d_in, const int* in_sizes, int n_in,
                              void* d_out, int out_size) {
    const float* x         = (const float*)d_in[0];
    const int*   m         = (const int*)d_in[1];
    const float* fc1_table = (const float*)d_in[2];
    const float* fc2_table = (const float*)d_in[3];
    float*       out       = (float*)d_out;

    group_kernel<<<32, 256>>>(m);
    fc1_kernel<<<dim3(HIDDEN / 128, MAX_TILES), 256>>>(x, fc1_table);
    fc2p_kernel<<<dim3(MAX_TILES, KSPLIT), 256>>>(fc2_table);
    combine_kernel<<<MAX_TILES, 256>>>(fc2_table, out);
}

// round 8
// speedup vs baseline: 1.3513x; 1.2097x over previous
#include <cuda_runtime.h>
#include <cuda_bf16.h>
#include <math.h>
#include <stdint.h>

#define IN_DIM   784
#define HIDDEN   512
#define STYLE    128
#define BATCH    2048
#define NUM_LABELS 10

#define BM 64
#define MAX_TILES (BATCH / BM + NUM_LABELS)   // 42
#define KSPLIT 4                              // fc2 K split: 512 / 4 = 128 per chunk

// Scratch (no allocations allowed -> __device__ globals)
__device__ int   g_perm[BATCH];
__device__ int   g_tileGroup[MAX_TILES];
__device__ int   g_tileStart[MAX_TILES];
__device__ int   g_tileRows[MAX_TILES];
__device__ __nv_bfloat16 g_h1[(BATCH + 128) * HIDDEN];          // padded
__device__ float g_part[KSPLIT * BATCH * STYLE];                // fc2 partials, 4 MB

// ---------------------------------------------------------------------------
// Helpers
// ---------------------------------------------------------------------------
__device__ __forceinline__ uint32_t f2bf2(float lo, float hi) {
    __nv_bfloat162 h = __floats2bfloat162_rn(lo, hi);
    return *reinterpret_cast<uint32_t*>(&h);
}

__device__ __forceinline__ void ldsm_x4(uint32_t& r0, uint32_t& r1, uint32_t& r2, uint32_t& r3,
                                        uint32_t saddr) {
    asm volatile("ldmatrix.sync.aligned.m8n8.x4.shared.b16 {%0,%1,%2,%3}, [%4];"
                 : "=r"(r0), "=r"(r1), "=r"(r2), "=r"(r3) : "r"(saddr));
}

__device__ __forceinline__ void ldsm_x4_t(uint32_t& r0, uint32_t& r1, uint32_t& r2, uint32_t& r3,
                                          uint32_t saddr) {
    asm volatile("ldmatrix.sync.aligned.m8n8.x4.trans.shared.b16 {%0,%1,%2,%3}, [%4];"
                 : "=r"(r0), "=r"(r1), "=r"(r2), "=r"(r3) : "r"(saddr));
}

__device__ __forceinline__ void mma16816_c(float* c, const uint32_t* a, const uint32_t* b) {
    asm volatile("mma.sync.aligned.m16n8k16.row.col.f32.bf16.bf16.f32 "
                 "{%0,%1,%2,%3}, {%4,%5,%6,%7}, {%8,%9}, {%0,%1,%2,%3};"
                 : "+f"(c[0]), "+f"(c[1]), "+f"(c[2]), "+f"(c[3])
                 : "r"(a[0]), "r"(a[1]), "r"(a[2]), "r"(a[3]), "r"(b[0]), "r"(b[1]));
}

// ---------------------------------------------------------------------------
// Kernel 1: grouping, 32 blocks. Every block redundantly computes the
// deterministic atomic-free counting sort over the 8KB label array (L2
// broadcast); block b writes perm entries for input indices [b*64,(b+1)*64);
// block 0 writes the tile table. Stable -> fully deterministic.
// ---------------------------------------------------------------------------
__global__ void group_kernel(const int* __restrict__ m) {
    __shared__ uint16_t h[NUM_LABELS][257];
    __shared__ int cnt[NUM_LABELS];
    __shared__ int baseS[NUM_LABELS];
    const int t = threadIdx.x, lane = t & 31, warp = t >> 5;

    int4 lv0 = ((const int4*)m)[t * 2];
    int4 lv1 = ((const int4*)m)[t * 2 + 1];
    int lab[8] = {lv0.x, lv0.y, lv0.z, lv0.w, lv1.x, lv1.y, lv1.z, lv1.w};

#pragma unroll
    for (int g = 0; g < NUM_LABELS; g++) {
        int c = 0;
#pragma unroll
        for (int j = 0; j < 8; j++) c += (lab[j] == g);
        h[g][t] = (uint16_t)c;
    }
    __syncthreads();

    for (int g = warp; g < NUM_LABELS; g += 8) {
        int s = 0;
#pragma unroll
        for (int j = 0; j < 8; j++) s += h[g][lane * 8 + j];
        int incl = s;
#pragma unroll
        for (int d = 1; d < 32; d <<= 1) {
            int v = __shfl_up_sync(0xffffffffu, incl, d);
            if (lane >= d) incl += v;
        }
        int run = incl - s;
#pragma unroll
        for (int j = 0; j < 8; j++) {
            int tt = lane * 8 + j;
            int v = h[g][tt];
            h[g][tt] = (uint16_t)run;
            run += v;
        }
        if (lane == 31) cnt[g] = run;
    }
    __syncthreads();

    if (t == 0) {
        int o = 0;
        for (int g = 0; g < NUM_LABELS; g++) { baseS[g] = o; o += cnt[g]; }
        if (blockIdx.x == 0) {                          // tile table
            int tile = 0;
            for (int g = 0; g < NUM_LABELS; g++) {
                int c = cnt[g], nt = (c + BM - 1) / BM;
                for (int j = 0; j < nt; j++) {
                    g_tileGroup[tile] = g;
                    g_tileStart[tile] = baseS[g] + j * BM;
                    g_tileRows[tile]  = min(BM, c - j * BM);
                    tile++;
                }
            }
            for (; tile < MAX_TILES; tile++) g_tileRows[tile] = 0;
        }
    }
    __syncthreads();

    if ((t >> 3) == (int)blockIdx.x) {                  // this block's 8 threads write
#pragma unroll
        for (int j = 0; j < 8; j++) {
            int g = lab[j];
            int rank = 0;
#pragma unroll
            for (int j2 = 0; j2 < 8; j2++)
                if (j2 < j) rank += (lab[j2] == g);
            g_perm[baseS[g] + (int)h[g][t] + rank] = t * 8 + j;
        }
    }
}

// ---------------------------------------------------------------------------
// Kernel 2: FC1 GEMM: 64x128 tile, BK=32, 256 thr, occ 2.
// ---------------------------------------------------------------------------
__global__ __launch_bounds__(256, 2) void fc1_kernel(const float* __restrict__ x,
                                                     const float* __restrict__ tab) {
    const int tile = blockIdx.y;
    const int rows = g_tileRows[tile];
    if (rows == 0) return;
    const int grp   = g_tileGroup[tile];
    const int start = g_tileStart[tile];
    const int n0    = blockIdx.x * 128;
    const float* W  = tab + (size_t)grp * ((IN_DIM + 1) * HIDDEN);

    __shared__ __align__(16) __nv_bfloat16 As[2][64][40];
    __shared__ __align__(16) __nv_bfloat16 Bs[2][32][136];
    __shared__ int rowIdx[64];

    const int t = threadIdx.x, lane = t & 31, warp = t >> 5;
    const int wm = warp >> 2, wn = warp & 3;

    if (t < 64) rowIdx[t] = (t < rows) ? g_perm[start + t] : -1;
    __syncthreads();

    int ar[2], ac4[2], alim[2]; const float* aptr[2];
#pragma unroll
    for (int p = 0; p < 2; p++) {
        int idx = t + p * 256;
        ar[p] = idx >> 3; ac4[p] = idx & 7;
        int gr = rowIdx[ar[p]];
        aptr[p] = x + (size_t)max(gr, 0) * IN_DIM + ac4[p] * 4;
        alim[p] = (gr >= 0) ? (IN_DIM - ac4[p] * 4) : 0;
    }
    int br[4], bc4[4];
#pragma unroll
    for (int p = 0; p < 4; p++) { int idx = t + p * 256; br[p] = idx >> 5; bc4[p] = idx & 31; }

    float acc[2][4][4];
#pragma unroll
    for (int mi = 0; mi < 2; mi++)
#pragma unroll
        for (int ni = 0; ni < 4; ni++)
#pragma unroll
            for (int j = 0; j < 4; j++) acc[mi][ni][j] = 0.f;

    const float4 Z4 = make_float4(0.f, 0.f, 0.f, 0.f);
    float4 aL[2], bL[4];
#pragma unroll
    for (int p = 0; p < 2; p++)
        aL[p] = (alim[p] > 0) ? *(const float4*)(aptr[p]) : Z4;
#pragma unroll
    for (int p = 0; p < 4; p++)
        bL[p] = *(const float4*)&W[(size_t)br[p] * HIDDEN + n0 + bc4[p] * 4];
#pragma unroll
    for (int p = 0; p < 2; p++) {
        *(uint32_t*)&As[0][ar[p]][ac4[p] * 4]     = f2bf2(aL[p].x, aL[p].y);
        *(uint32_t*)&As[0][ar[p]][ac4[p] * 4 + 2] = f2bf2(aL[p].z, aL[p].w);
    }
#pragma unroll
    for (int p = 0; p < 4; p++) {
        *(uint32_t*)&Bs[0][br[p]][bc4[p] * 4]     = f2bf2(bL[p].x, bL[p].y);
        *(uint32_t*)&Bs[0][br[p]][bc4[p] * 4 + 2] = f2bf2(bL[p].z, bL[p].w);
    }
    __syncthreads();

    const int NIT = (IN_DIM + 31) / 32;    // 25
    for (int it = 0; it < NIT; ++it) {
        const int cur = it & 1;
        if (it + 1 < NIT) {
            const int k0 = (it + 1) * 32;
#pragma unroll
            for (int p = 0; p < 2; p++)
                aL[p] = (k0 < alim[p]) ? *(const float4*)(aptr[p] + k0) : Z4;
#pragma unroll
            for (int p = 0; p < 4; p++) {
                int kr = k0 + br[p];
                const float4 v = *(const float4*)&W[(size_t)min(kr, IN_DIM) * HIDDEN + n0 + bc4[p] * 4];
                bL[p] = (kr < IN_DIM) ? v : Z4;
            }
        }

        uint32_t a[2][2][4], b[2][4][2];
#pragma unroll
        for (int mi = 0; mi < 2; mi++)
#pragma unroll
            for (int kh = 0; kh < 2; kh++) {
                uint32_t sa = (uint32_t)__cvta_generic_to_shared(
                    &As[cur][wm * 32 + mi * 16 + (lane & 15)][kh * 16 + (lane >> 4) * 8]);
                ldsm_x4(a[mi][kh][0], a[mi][kh][1], a[mi][kh][2], a[mi][kh][3], sa);
            }
#pragma unroll
        for (int kh = 0; kh < 2; kh++)
#pragma unroll
            for (int half = 0; half < 2; half++) {
                uint32_t sb = (uint32_t)__cvta_generic_to_shared(
                    &Bs[cur][kh * 16 + (lane & 7) + ((lane >> 3) & 1) * 8]
                       [wn * 32 + half * 16 + (lane >> 4) * 8]);
                ldsm_x4_t(b[kh][2 * half][0], b[kh][2 * half][1],
                          b[kh][2 * half + 1][0], b[kh][2 * half + 1][1], sb);
            }
#pragma unroll
        for (int kh = 0; kh < 2; kh++)
#pragma unroll
            for (int mi = 0; mi < 2; mi++)
#pragma unroll
                for (int ni = 0; ni < 4; ni++)
                    mma16816_c(acc[mi][ni], a[mi][kh], b[kh][ni]);

        if (it + 1 < NIT) {
            const int nxt = cur ^ 1;
#pragma unroll
            for (int p = 0; p < 2; p++) {
                *(uint32_t*)&As[nxt][ar[p]][ac4[p] * 4]     = f2bf2(aL[p].x, aL[p].y);
                *(uint32_t*)&As[nxt][ar[p]][ac4[p] * 4 + 2] = f2bf2(aL[p].z, aL[p].w);
            }
#pragma unroll
            for (int p = 0; p < 4; p++) {
                *(uint32_t*)&Bs[nxt][br[p]][bc4[p] * 4]     = f2bf2(bL[p].x, bL[p].y);
                *(uint32_t*)&Bs[nxt][br[p]][bc4[p] * 4 + 2] = f2bf2(bL[p].z, bL[p].w);
            }
        }
        __syncthreads();
    }

    const float* bias = W + (size_t)IN_DIM * HIDDEN + n0;
    uint32_t* h1u = (uint32_t*)g_h1;
#pragma unroll
    for (int ni = 0; ni < 4; ni++) {
        int c = wn * 32 + ni * 8 + (lane & 3) * 2;
        float2 bb = *(const float2*)&bias[c];
#pragma unroll
        for (int mi = 0; mi < 2; mi++) {
            int r0 = wm * 32 + mi * 16 + (lane >> 2);
            if (r0 < rows) {
                float vx = fmaxf(acc[mi][ni][0] + bb.x, 0.f);
                float vy = fmaxf(acc[mi][ni][1] + bb.y, 0.f);
                h1u[((size_t)(start + r0) * HIDDEN + n0 + c) >> 1] = f2bf2(vx, vy);
            }
            int r1 = r0 + 8;
            if (r1 < rows) {
                float vx = fmaxf(acc[mi][ni][2] + bb.x, 0.f);
                float vy = fmaxf(acc[mi][ni][3] + bb.y, 0.f);
                h1u[((size_t)(start + r1) * HIDDEN + n0 + c) >> 1] = f2bf2(vx, vy);
            }
        }
    }
}

// ---------------------------------------------------------------------------
// Kernel 3: FC2 split-K partial. grid (42 tiles, 4 kchunks) = 168 blocks.
// Each: 64x128 output for K=128 (2 macro-iters of BK=64). Partials -> g_part.
// ---------------------------------------------------------------------------
__global__ __launch_bounds__(256, 2) void fc2p_kernel(const float* __restrict__ tab) {
    const int tile = blockIdx.x;
    const int kc   = blockIdx.y;
    const int rows = g_tileRows[tile];
    if (rows == 0) return;
    const int grp   = g_tileGroup[tile];
    const int start = g_tileStart[tile];
    const float* W  = tab + (size_t)grp * ((HIDDEN + 1) * STYLE) + (size_t)(kc * 128) * STYLE;

    __shared__ __align__(16) __nv_bfloat16 As[64][136];   // 64 rows x K=128 (+8 pad)
    __shared__ __align__(16) __nv_bfloat16 Bs[64][136];   // 64 K-rows x N=128 (+8 pad)

    const int t = threadIdx.x, lane = t & 31, warp = t >> 5;
    const int wm = warp >> 2, wn = warp & 3;

    // Load A in full: 64 rows x 128 bf16 from g_h1 (permuted dense) = 512 uint4
    {
        const __nv_bfloat16* h1 = g_h1 + (size_t)start * HIDDEN + kc * 128;
#pragma unroll
        for (int p = 0; p < 2; p++) {
            int idx = t + p * 256;
            int r = idx >> 3, q = idx & 7;
            *(uint4*)&As[r][q * 8] = *(const uint4*)(h1 + (size_t)r * HIDDEN + q * 8);
        }
    }

    float acc[2][4][4];
#pragma unroll
    for (int mi = 0; mi < 2; mi++)
#pragma unroll
        for (int ni = 0; ni < 4; ni++)
#pragma unroll
            for (int j = 0; j < 4; j++) acc[mi][ni][j] = 0.f;

#pragma unroll
    for (int h2 = 0; h2 < 2; h2++) {
        // Load B half: W rows h2*64..+64, 128 cols fp32 -> bf16. 64x32 float4, 8/thread
#pragma unroll
        for (int p = 0; p < 8; p++) {
            int idx = t + p * 256;
            int r = idx >> 5, c4 = idx & 31;
            float4 v = *(const float4*)&W[(size_t)(h2 * 64 + r) * STYLE + c4 * 4];
            *(uint32_t*)&Bs[r][c4 * 4]     = f2bf2(v.x, v.y);
            *(uint32_t*)&Bs[r][c4 * 4 + 2] = f2bf2(v.z, v.w);
        }
        __syncthreads();

#pragma unroll
        for (int kh = 0; kh < 4; kh++) {
            uint32_t a[2][4], b[4][2];
#pragma unroll
            for (int mi = 0; mi < 2; mi++) {
                uint32_t sa = (uint32_t)__cvta_generic_to_shared(
                    &As[wm * 32 + mi * 16 + (lane & 15)][h2 * 64 + kh * 16 + (lane >> 4) * 8]);
                ldsm_x4(a[mi][0], a[mi][1], a[mi][2], a[mi][3], sa);
            }
#pragma unroll
            for (int half = 0; half < 2; half++) {
                uint32_t sb = (uint32_t)__cvta_generic_to_shared(
                    &Bs[kh * 16 + (lane & 7) + ((lane >> 3) & 1) * 8]
                       [wn * 32 + half * 16 + (lane >> 4) * 8]);
                ldsm_x4_t(b[2 * half][0], b[2 * half][1], b[2 * half + 1][0], b[2 * half + 1][1], sb);
            }
#pragma unroll
            for (int mi = 0; mi < 2; mi++)
#pragma unroll
                for (int ni = 0; ni < 4; ni++)
                    mma16816_c(acc[mi][ni], a[mi], b[ni]);
        }
        __syncthreads();
    }

    // Store partials (permuted dense rows, no bias/activation)
    float* P = g_part + (size_t)kc * BATCH * STYLE;
#pragma unroll
    for (int ni = 0; ni < 4; ni++) {
        int c = wn * 32 + ni * 8 + (lane & 3) * 2;
#pragma unroll
        for (int mi = 0; mi < 2; mi++) {
            int r0 = wm * 32 + mi * 16 + (lane >> 2);
            if (r0 < rows)
                *(float2*)&P[(size_t)(start + r0) * STYLE + c] =
                    make_float2(acc[mi][ni][0], acc[mi][ni][1]);
            int r1 = r0 + 8;
            if (r1 < rows)
                *(float2*)&P[(size_t)(start + r1) * STYLE + c] =
                    make_float2(acc[mi][ni][2], acc[mi][ni][3]);
        }
    }
}

// ---------------------------------------------------------------------------
// Kernel 4: FLAT combine. 65,536 threads, one float4 item each.
// pos = permuted row, label via m[g_perm[pos]] (warp-broadcast), fully
// coalesced partial reads. BW-bound instead of latency-bound.
// ---------------------------------------------------------------------------
__global__ __launch_bounds__(256) void combine_kernel(const int*   __restrict__ m,
                                                      const float* __restrict__ tab,
                                                      float*       __restrict__ out) {
    const int idx = blockIdx.x * 256 + threadIdx.x;     // 0 .. BATCH*32-1
    const int pos = idx >> 5;                           // permuted row
    const int c4  = idx & 31;                           // float4 column

    const int orow = g_perm[pos];                       // same for whole warp -> broadcast
    const int grp  = m[orow];
    const float* bias = tab + (size_t)grp * ((HIDDEN + 1) * STYLE) + (size_t)HIDDEN * STYLE;
    float4 bb = *(const float4*)&bias[c4 * 4];

    size_t off = (size_t)pos * STYLE + c4 * 4;
    float4 s0 = *(const float4*)&g_part[off];
    float4 s1 = *(const float4*)&g_part[(size_t)1 * BATCH * STYLE + off];
    float4 s2 = *(const float4*)&g_part[(size_t)2 * BATCH * STYLE + off];
    float4 s3 = *(const float4*)&g_part[(size_t)3 * BATCH * STYLE + off];
    float4 v;
    v.x = 1.f / (1.f + __expf(-(s0.x + s1.x + s2.x + s3.x + bb.x)));
    v.y = 1.f / (1.f + __expf(-(s0.y + s1.y + s2.y + s3.y + bb.y)));
    v.z = 1.f / (1.f + __expf(-(s0.z + s1.z + s2.z + s3.z + bb.z)));
    v.w = 1.f / (1.f + __expf(-(s0.w + s1.w + s2.w + s3.w + bb.w)));
    *(float4*)&out[(size_t)orow * STYLE + c4 * 4] = v;
}

extern "C" void kernel_launch(void* const* d_in, const int* in_sizes, int n_in,
                              void* d_out, int out_size) {
    const float* x         = (const float*)d_in[0];
    const int*   m         = (const int*)d_in[1];
    const float* fc1_table = (const float*)d_in[2];
    const float* fc2_table = (const float*)d_in[3];
    float*       out       = (float*)d_out;

    group_kernel<<<32, 256>>>(m);
    fc1_kernel<<<dim3(HIDDEN / 128, MAX_TILES), 256>>>(x, fc1_table);
    fc2p_kernel<<<dim3(MAX_TILES, KSPLIT), 256>>>(fc2_table);
    combine_kernel<<<(BATCH * 32) / 256, 256>>>(m, fc2_table, out);
}